// round 14
// baseline (speedup 1.0000x reference)
#include <cuda_runtime.h>
#include <cstdint>
#include <math.h>

// ---------------- problem constants ----------------
#define BDIM 256
#define DIN 2048
#define HID 2048
#define DCTX 1024
#define NSEG 10
#define NR (HID * NSEG) /* 20480 */
#define OUTD 100
#define KWIN 102

#define DW 128    // ELL row width for dendrite rows (mean nz 51.2)
#define FW 192    // ELL width for FF rows (mean nz 102.4)

typedef unsigned long long u64;

// ---------------- scratch (no allocations allowed) ----------------
__device__ float g_ctxT[DCTX * BDIM];       // 1 MB  context transposed [c][b]
__device__ float g_xT[DIN * BDIM];          // 2 MB  x transposed [c][b]
__device__ float g_hT[HID * BDIM];          // 2 MB  layer-1 winners transposed [c][b]
__device__ float g_yT[HID * BDIM];          // 2 MB  ff pre-activation [n][b]
__device__ float g_gT1[HID * BDIM];         // 2 MB  dendrite gate layer 1 [u][b]
__device__ float g_gT2[HID * BDIM];         // 2 MB  dendrite gate layer 2 [u][b]
__device__ float g_h2[BDIM * HID];          // 2 MB  layer-2 winners, row-major
__device__ __align__(16) u64 g_ellD1[(size_t)NR * DW];   // 21 MB ELL (dendrite L1)
__device__ __align__(16) u64 g_ellD2[(size_t)NR * DW];   // 21 MB ELL (dendrite L2)
__device__ int4 g_cntQ1[NR];   // entry counts at col <256,<512,<768,total
__device__ int4 g_cntQ2[NR];
__device__ __align__(16) u64 g_ellF1[(size_t)HID * FW];  // 3 MB  ELL (ff L1)
__device__ __align__(16) u64 g_ellF2[(size_t)HID * FW];  // 3 MB  ELL (ff L2)
__device__ int  g_cntF1[HID];
__device__ int  g_cntF2[HID];

// =====================================================================
// warp-per-row ELL compaction: ballot+popc positioning, depth-2
// register prefetch (4 LDG.128 in flight). Ascending column order.
// entry = (f32 weight bits << 32) | (col * mult).
// cq != 0: also record counts at chunk boundaries 2,4,6 (cols 256/512/768).
// =====================================================================
__device__ __forceinline__
void build_row(const float* __restrict__ W, const float* __restrict__ M,
               u64* __restrict__ ell, int* __restrict__ cnt, int4* __restrict__ cq,
               int K, int width, int mult, int row, int lane) {
    const float4* wr = (const float4*)(W + (size_t)row * K);
    const float4* mr = (const float4*)(M + (size_t)row * K);
    u64* er = ell + (size_t)row * width;
    const int chunks = K >> 7;  // 128 floats per chunk (float4 per lane)
    const unsigned below = (1u << lane) - 1u;
    int base = 0, q1 = 0, q2 = 0, q3 = 0;
    float4 w0 = wr[lane],      m0 = mr[lane];
    float4 w1 = wr[32 + lane], m1 = mr[32 + lane];  // chunks >= 4 always
    for (int c = 0; c < chunks; ++c) {
        float4 wn, mn;
        if (c + 2 < chunks) {
            wn = wr[(c + 2) * 32 + lane];
            mn = mr[(c + 2) * 32 + lane];
        }
        const unsigned bx = __ballot_sync(0xffffffffu, m0.x != 0.f);
        const unsigned by = __ballot_sync(0xffffffffu, m0.y != 0.f);
        const unsigned bz = __ballot_sync(0xffffffffu, m0.z != 0.f);
        const unsigned bw = __ballot_sync(0xffffffffu, m0.w != 0.f);
        int p = base + __popc(bx & below) + __popc(by & below)
                     + __popc(bz & below) + __popc(bw & below);
        const int col0 = c * 128 + lane * 4;
        if (m0.x != 0.f && p < width) er[p++] = ((u64)__float_as_uint(w0.x) << 32) | (unsigned)((col0 + 0) * mult);
        if (m0.y != 0.f && p < width) er[p++] = ((u64)__float_as_uint(w0.y) << 32) | (unsigned)((col0 + 1) * mult);
        if (m0.z != 0.f && p < width) er[p++] = ((u64)__float_as_uint(w0.z) << 32) | (unsigned)((col0 + 2) * mult);
        if (m0.w != 0.f && p < width) er[p++] = ((u64)__float_as_uint(w0.w) << 32) | (unsigned)((col0 + 3) * mult);
        base += __popc(bx) + __popc(by) + __popc(bz) + __popc(bw);
        if (c == 1) q1 = base;
        else if (c == 3) q2 = base;
        else if (c == 5) q3 = base;
        w0 = w1; m0 = m1;
        w1 = wn; m1 = mn;
    }
    if (lane == 0) {
        const int t = base < width ? base : width;
        if (cq) cq[row] = make_int4(q1 < width ? q1 : width,
                                    q2 < width ? q2 : width,
                                    q3 < width ? q3 : width, t);
        else cnt[row] = t;
    }
}

// =====================================================================
// K1a: fused builds only.
// Dendrite entries: mult=512 (128-batch float4 tile), quarter bounds.
// FF entries: mult=1024 (256-batch float tile).
// Block ranges:
//   [0,2560)      build dendrite L1   (8 rows/block)
//   [2560,5120)   build dendrite L2
//   [5120,5376)   build FF L1
//   [5376,5632)   build FF L2
// =====================================================================
__global__ __launch_bounds__(256)
void prep_build(const float* __restrict__ segW1, const float* __restrict__ maskS1,
                const float* __restrict__ segW2, const float* __restrict__ maskS2,
                const float* __restrict__ W1, const float* __restrict__ maskW1,
                const float* __restrict__ W2, const float* __restrict__ maskW2) {
    const int bid = blockIdx.x;
    const int tid = threadIdx.x;
    const int lane = tid & 31;
    const int wid = tid >> 5;

    if (bid < 5120) {  // dendrite builds
        const int part = bid / 2560;                 // 0 or 1
        const int row = (bid % 2560) * 8 + wid;      // 0..20479
        if (part == 0) build_row(segW1, maskS1, g_ellD1, (int*)0, g_cntQ1, DCTX, DW, 512, row, lane);
        else           build_row(segW2, maskS2, g_ellD2, (int*)0, g_cntQ2, DCTX, DW, 512, row, lane);
        return;
    }
    // FF builds
    const int part = (bid - 5120) >> 8;              // 0 or 1 (256 blocks each)
    const int row = ((bid - 5120) & 255) * 8 + wid;
    if (part == 0) build_row(W1, maskW1, g_ellF1, g_cntF1, (int4*)0, DIN, FW, 1024, row, lane);
    else           build_row(W2, maskW2, g_ellF2, g_cntF2, (int4*)0, HID, FW, 1024, row, lane);
}

// =====================================================================
// K1b: both transposes. Block ranges: [0,256) ctx, [256,768) x.
// in[R=256][C] -> out[C][256]
// =====================================================================
__global__ __launch_bounds__(256)
void prep_transpose(const float* __restrict__ ctx, const float* __restrict__ x) {
    __shared__ float t[32][33];
    const int bid = blockIdx.x;
    const int tid = threadIdx.x;
    const float* in;
    float* outp;
    int C, lb;
    if (bid < 256) { in = ctx; outp = g_ctxT; C = DCTX; lb = bid; }
    else           { in = x;   outp = g_xT;   C = DIN;  lb = bid - 256; }
    const int nbx = C >> 5;
    const int c0 = (lb % nbx) * 32;
    const int r0 = (lb / nbx) * 32;
    const int xx = tid & 31, yy = tid >> 5;
#pragma unroll
    for (int i = 0; i < 32; i += 8)
        t[yy + i][xx] = in[(size_t)(r0 + yy + i) * C + c0 + xx];
    __syncthreads();
#pragma unroll
    for (int i = 0; i < 32; i += 8)
        outp[(size_t)(c0 + yy + i) * BDIM + r0 + xx] = t[xx][yy + i];
}

// =====================================================================
// K2: fused dendrite spMM + gate, 128-batch / 4-c-pass version.
// 512 threads (16 warps, 128-reg budget); warp = 2 units; lane = 4
// batches (float4 LDS.128). smem tile = ctx[256 c][128 b] = 128 KB,
// swapped across 4 passes; entries split at quarter boundaries.
// Per entry: 1 broadcast LDG.64 + 4 LDS-wf per 128 batches.
// grid 256: [layer(2)][bg(2)][blk(64)].   <-- PROFILED (user slot 4)
// =====================================================================
__global__ __launch_bounds__(512, 1)
void dspmm_gate2(const float* __restrict__ ctxT) {
    extern __shared__ float s[];  // 256 * 128 floats = 128 KB
    const int id = blockIdx.x;
    const int layer = id >> 7;
    const int bg = (id >> 6) & 1;
    const int blk = id & 63;
    const u64* __restrict__ ell = layer ? g_ellD2 : g_ellD1;
    const int4* __restrict__ cq = layer ? g_cntQ2 : g_cntQ1;
    float* __restrict__ gT = layer ? g_gT2 : g_gT1;

    const int b0 = bg * 128;
    const int tid = threadIdx.x;
    const int wid = tid >> 5, lane = tid & 31;
    const char* sb = (const char*)s + lane * 16;
    const int u0 = blk * 32 + wid * 2;       // first of 2 units
    const int r0 = u0 * NSEG;                // rows r0 .. r0+19 contiguous
    int4 q = make_int4(0, 0, 0, 0);
    if (lane < 2 * NSEG) q = cq[r0 + lane];

    float4 accs[2][NSEG];
#pragma unroll
    for (int iu = 0; iu < 2; ++iu)
#pragma unroll
        for (int sg = 0; sg < NSEG; ++sg) accs[iu][sg] = make_float4(0.f, 0.f, 0.f, 0.f);

#pragma unroll
    for (int pass = 0; pass < 4; ++pass) {
        if (pass) __syncthreads();  // all warps done reading previous tile
        // stage ctx[pass*256 .. +256)[b0 .. b0+127]
        for (int i = tid; i < 256 * 32; i += 512) {
            const int c = i >> 5, qq = (i & 31) * 4;
            *(float4*)&s[c * 128 + qq] =
                *(const float4*)&ctxT[(size_t)(pass * 256 + c) * 256 + b0 + qq];
        }
        __syncthreads();
        // per-lane boundary pair for this pass (own row)
        const int jlo_own = (pass == 0) ? 0 : ((pass == 1) ? q.x : ((pass == 2) ? q.y : q.z));
        const int jhi_own = (pass == 0) ? q.x : ((pass == 1) ? q.y : ((pass == 2) ? q.z : q.w));
        const unsigned off = (unsigned)pass * 131072u;  // 256 cols * 512 B
#pragma unroll
        for (int iu = 0; iu < 2; ++iu) {
#pragma unroll
            for (int sg = 0; sg < NSEG; ++sg) {
                const int src = iu * NSEG + sg;
                const int j0 = __shfl_sync(0xffffffffu, jlo_own, src);
                const int j1 = __shfl_sync(0xffffffffu, jhi_own, src);
                const u64* e = ell + (size_t)(r0 + src) * DW;
                float4 a = accs[iu][sg];
                int j = j0;
                for (; j + 2 <= j1; j += 2) {
                    const u64 e0 = e[j], e1 = e[j + 1];
                    const float w0 = __uint_as_float((unsigned)(e0 >> 32));
                    const float w1 = __uint_as_float((unsigned)(e1 >> 32));
                    const float4 v0 = *(const float4*)(sb + ((unsigned)e0 - off));
                    const float4 v1 = *(const float4*)(sb + ((unsigned)e1 - off));
                    a.x += w0 * v0.x; a.y += w0 * v0.y; a.z += w0 * v0.z; a.w += w0 * v0.w;
                    a.x += w1 * v1.x; a.y += w1 * v1.y; a.z += w1 * v1.z; a.w += w1 * v1.w;
                }
                if (j < j1) {
                    const u64 e0 = e[j];
                    const float w0 = __uint_as_float((unsigned)(e0 >> 32));
                    const float4 v0 = *(const float4*)(sb + ((unsigned)e0 - off));
                    a.x += w0 * v0.x; a.y += w0 * v0.y; a.z += w0 * v0.z; a.w += w0 * v0.w;
                }
                accs[iu][sg] = a;
            }
        }
    }
    // first-occurrence abs-argmax (strict >) + sigmoid, per batch component
#pragma unroll
    for (int iu = 0; iu < 2; ++iu) {
        float4 best = accs[iu][0];
        float4 ba = make_float4(fabsf(best.x), fabsf(best.y), fabsf(best.z), fabsf(best.w));
#pragma unroll
        for (int sg = 1; sg < NSEG; ++sg) {
            const float4 v = accs[iu][sg];
            float a;
            a = fabsf(v.x); if (a > ba.x) { ba.x = a; best.x = v.x; }
            a = fabsf(v.y); if (a > ba.y) { ba.y = a; best.y = v.y; }
            a = fabsf(v.z); if (a > ba.z) { ba.z = a; best.z = v.z; }
            a = fabsf(v.w); if (a > ba.w) { ba.w = a; best.w = v.w; }
        }
        const float4 g = make_float4(1.0f / (1.0f + __expf(-best.x)),
                                     1.0f / (1.0f + __expf(-best.y)),
                                     1.0f / (1.0f + __expf(-best.z)),
                                     1.0f / (1.0f + __expf(-best.w)));
        *(float4*)&gT[(size_t)(u0 + iu) * 256 + b0 + lane * 4] = g;
    }
}

// =====================================================================
// FF spMM (gate applied in kwinners): yT[r][b] = bias[r] + sum w*xT[c][b]
// One block per output row (2048 blocks); entries staged in smem (16B
// aligned), read back as LDS.128 pairs; unroll 8 for L2 MLP.
// =====================================================================
__global__ __launch_bounds__(256)
void fspmm(const float* __restrict__ xT, const u64* __restrict__ ell,
           const int* __restrict__ cnt, const float* __restrict__ bias,
           float* __restrict__ yT) {
    __shared__ alignas(16) u64 fe[FW];
    const int r = blockIdx.x;
    const int tid = threadIdx.x;
    const int n = cnt[r];
    for (int j = tid; j < n; j += 256) fe[j] = ell[(size_t)r * FW + j];
    __syncthreads();
    const char* xb = (const char*)xT + tid * 4;
    const ulonglong2* fe2 = (const ulonglong2*)fe;
    float acc = 0.f;
    int j = 0;
    for (; j + 8 <= n; j += 8) {
        float p = 0.f;
#pragma unroll
        for (int q = 0; q < 4; ++q) {
            const ulonglong2 e = fe2[(j >> 1) + q];
            p += __uint_as_float((unsigned)(e.x >> 32)) * *(const float*)(xb + (unsigned)e.x);
            p += __uint_as_float((unsigned)(e.y >> 32)) * *(const float*)(xb + (unsigned)e.y);
        }
        acc += p;
    }
    for (; j < n; ++j) {
        const u64 e = fe[j];
        acc += __uint_as_float((unsigned)(e >> 32)) * *(const float*)(xb + (unsigned)e);
    }
    yT[(size_t)r * 256 + tid] = acc + bias[r];
}

// =====================================================================
// k-winners with fused gate: val = yT[i][b] * gT[i][b]; exact top-KWIN
// via 4-pass radix select; single-warp shfl suffix scan bin selection.
// mode 0 -> transposed hT[i][b]; mode 1 -> row-major h2[b][i].
// =====================================================================
__global__ __launch_bounds__(256)
void kwinners_k(const float* __restrict__ yT, const float* __restrict__ gT,
                float* __restrict__ outT, float* __restrict__ outN, int mode) {
    __shared__ unsigned keys[HID];
    __shared__ int hist[256];
    __shared__ int s_digit;
    __shared__ int s_need;
    const int b = blockIdx.x, tid = threadIdx.x;
    for (int i = tid; i < HID; i += 256) {
        const float v = yT[(size_t)i * 256 + b] * gT[(size_t)i * 256 + b];
        unsigned u = __float_as_uint(v);
        u = (u & 0x80000000u) ? ~u : (u | 0x80000000u);  // monotonic ascending
        keys[i] = u;
    }
    if (tid == 0) s_need = KWIN;
    __syncthreads();

    unsigned prefix = 0, pmask = 0;
    for (int pass = 0; pass < 4; ++pass) {
        const int shift = 24 - 8 * pass;
        hist[tid] = 0;
        __syncthreads();
        for (int i = tid; i < HID; i += 256) {
            const unsigned u = keys[i];
            if ((u & pmask) == prefix) atomicAdd(&hist[(u >> shift) & 255], 1);
        }
        __syncthreads();
        if (tid < 32) {
            const int need = s_need;
            const int base = tid * 8;
            int gs = 0;
#pragma unroll
            for (int k = 0; k < 8; ++k) gs += hist[base + k];
            int S = gs;  // inclusive suffix sum across lanes
#pragma unroll
            for (int o = 1; o < 32; o <<= 1) {
                const int t = __shfl_down_sync(0xffffffffu, S, o);
                if (tid + o < 32) S += t;
            }
            int Snext = __shfl_down_sync(0xffffffffu, S, 1);
            if (tid == 31) Snext = 0;
            if (S >= need && Snext < need) {  // unique crossing lane
                int c = Snext;
#pragma unroll
                for (int k = 7; k >= 0; --k) {
                    const int hb = hist[base + k];
                    if (c + hb >= need) { s_digit = base + k; s_need = need - c; break; }
                    c += hb;
                }
            }
        }
        __syncthreads();
        prefix |= ((unsigned)s_digit) << shift;
        pmask |= 0xFFu << shift;
    }
    const unsigned thr = prefix;  // key of the KWIN-th largest
    for (int i = tid; i < HID; i += 256) {
        const unsigned u = keys[i];
        float val = 0.f;
        if (u >= thr) {
            const unsigned ob = (u & 0x80000000u) ? (u & 0x7FFFFFFFu) : ~u;
            val = __uint_as_float(ob);
        }
        if (mode == 0) outT[(size_t)i * 256 + b] = val;
        else           outN[(size_t)b * HID + i] = val;
    }
}

// =====================================================================
// EiDense head: out[b,o] = h.Wex[o] - (h.Wix)*Wei[o] + b_out[o]
// =====================================================================
__global__ __launch_bounds__(256)
void head_kernel(const float* __restrict__ h, const float* __restrict__ Wex,
                 const float* __restrict__ Wix, const float* __restrict__ Wei,
                 const float* __restrict__ bo, float* __restrict__ out) {
    __shared__ alignas(16) float sh[4][HID];
    __shared__ float st[4];
    const int b0 = blockIdx.x * 4;
    const int tid = threadIdx.x;
    for (int i = tid; i < 4 * HID; i += 256)
        (&sh[0][0])[i] = h[(size_t)b0 * HID + i];
    __syncthreads();
    const int wid = tid >> 5;
    const int lane = tid & 31;
    if (wid < 4) {
        float p = 0.f;
        for (int u = lane; u < HID; u += 32) p += sh[wid][u] * Wix[u];
#pragma unroll
        for (int o = 16; o; o >>= 1) p += __shfl_xor_sync(0xffffffffu, p, o);
        if (lane == 0) st[wid] = p;
    }
    __syncthreads();
    for (int o = wid; o < OUTD; o += 8) {
        float a0 = 0.f, a1 = 0.f, a2 = 0.f, a3 = 0.f;
        const float* wrow = Wex + (size_t)o * HID;
        for (int u = lane; u < HID; u += 32) {
            const float w = wrow[u];
            a0 += sh[0][u] * w;
            a1 += sh[1][u] * w;
            a2 += sh[2][u] * w;
            a3 += sh[3][u] * w;
        }
#pragma unroll
        for (int sft = 16; sft; sft >>= 1) {
            a0 += __shfl_xor_sync(0xffffffffu, a0, sft);
            a1 += __shfl_xor_sync(0xffffffffu, a1, sft);
            a2 += __shfl_xor_sync(0xffffffffu, a2, sft);
            a3 += __shfl_xor_sync(0xffffffffu, a3, sft);
        }
        if (lane == 0) {
            const float we = Wei[o];
            const float bb = bo[o];
            out[(size_t)(b0 + 0) * OUTD + o] = a0 - st[0] * we + bb;
            out[(size_t)(b0 + 1) * OUTD + o] = a1 - st[1] * we + bb;
            out[(size_t)(b0 + 2) * OUTD + o] = a2 - st[2] * we + bb;
            out[(size_t)(b0 + 3) * OUTD + o] = a3 - st[3] * we + bb;
        }
    }
}

// =====================================================================
// launch — dspmm_gate2 kept at user-launch #4 (ncu -s 5 slot)
// =====================================================================
extern "C" void kernel_launch(void* const* d_in, const int* in_sizes, int n_in,
                              void* d_out, int out_size) {
    const float* x      = (const float*)d_in[0];
    const float* ctx    = (const float*)d_in[1];
    const float* W1     = (const float*)d_in[2];
    const float* b1     = (const float*)d_in[3];
    const float* segW1  = (const float*)d_in[4];
    const float* maskW1 = (const float*)d_in[5];
    const float* maskS1 = (const float*)d_in[6];
    const float* W2     = (const float*)d_in[7];
    const float* b2     = (const float*)d_in[8];
    const float* segW2  = (const float*)d_in[9];
    const float* maskW2 = (const float*)d_in[10];
    const float* maskS2 = (const float*)d_in[11];
    const float* Wex    = (const float*)d_in[12];
    const float* Wix    = (const float*)d_in[13];
    const float* Wei    = (const float*)d_in[14];
    const float* bo     = (const float*)d_in[15];
    float* out = (float*)d_out;

    float *ctxT, *xT, *hT, *yT, *gT1, *gT2, *h2;
    u64 *ellF1, *ellF2;
    int *cntF1, *cntF2;
    cudaGetSymbolAddress((void**)&ctxT,  g_ctxT);
    cudaGetSymbolAddress((void**)&xT,    g_xT);
    cudaGetSymbolAddress((void**)&hT,    g_hT);
    cudaGetSymbolAddress((void**)&yT,    g_yT);
    cudaGetSymbolAddress((void**)&gT1,   g_gT1);
    cudaGetSymbolAddress((void**)&gT2,   g_gT2);
    cudaGetSymbolAddress((void**)&h2,    g_h2);
    cudaGetSymbolAddress((void**)&ellF1, g_ellF1);
    cudaGetSymbolAddress((void**)&ellF2, g_ellF2);
    cudaGetSymbolAddress((void**)&cntF1, g_cntF1);
    cudaGetSymbolAddress((void**)&cntF2, g_cntF2);

    const int dsmem = 256 * 128 * 4;  // 128 KB
    cudaFuncSetAttribute(dspmm_gate2, cudaFuncAttributeMaxDynamicSharedMemorySize, dsmem);

    // (1) all four ELL builds fused (ballot-scan, depth-2 prefetch,
    //     +quarter boundaries for dendrites)
    prep_build<<<5632, 256>>>(segW1, maskS1, segW2, maskS2,
                              W1, maskW1, W2, maskW2);
    // (2) both transposes
    prep_transpose<<<768, 256>>>(ctx, x);
    // (3) layer 1 FF (independent of dendrite path)
    fspmm<<<HID, 256>>>(xT, ellF1, cntF1, b1, yT);
    // (4) both layers' dendrite gates, 128-batch / 4-pass  <-- ncu slot
    dspmm_gate2<<<256, 512, dsmem>>>(ctxT);
    // (5) layer 1 k-winners (applies gate 1) -> hT
    kwinners_k<<<BDIM, 256>>>(yT, gT1, hT, h2, 0);
    // (6) layer 2 FF
    fspmm<<<HID, 256>>>(hT, ellF2, cntF2, b2, yT);
    // (7) layer 2 k-winners (applies gate 2) -> h2 row-major
    kwinners_k<<<BDIM, 256>>>(yT, gT2, hT, h2, 1);
    // (8) EiDense head
    head_kernel<<<BDIM / 4, 256>>>(h2, Wex, Wix, Wei, bo, out);
}

// round 15
// speedup vs baseline: 1.0732x; 1.0732x over previous
#include <cuda_runtime.h>
#include <cstdint>
#include <math.h>

// ---------------- problem constants ----------------
#define BDIM 256
#define DIN 2048
#define HID 2048
#define DCTX 1024
#define NSEG 10
#define NR (HID * NSEG) /* 20480 */
#define OUTD 100
#define KWIN 102

#define DW 128    // ELL row width for dendrite rows (mean nz 51.2)
#define FW 192    // ELL width for FF rows (mean nz 102.4)

typedef unsigned long long u64;

// ---------------- scratch (no allocations allowed) ----------------
__device__ float g_ctxT[DCTX * BDIM];       // 1 MB  context transposed [c][b]
__device__ float g_xT[DIN * BDIM];          // 2 MB  x transposed [c][b]
__device__ float g_hT[HID * BDIM];          // 2 MB  layer-1 winners transposed [c][b]
__device__ float g_yT[HID * BDIM];          // 2 MB  ff pre-activation [n][b]
__device__ float g_gT1[HID * BDIM];         // 2 MB  dendrite gate layer 1 [u][b]
__device__ float g_gT2[HID * BDIM];         // 2 MB  dendrite gate layer 2 [u][b]
__device__ float g_h2[BDIM * HID];          // 2 MB  layer-2 winners, row-major
__device__ __align__(16) u64 g_ellD1[(size_t)NR * DW];   // 21 MB ELL (dendrite L1)
__device__ __align__(16) u64 g_ellD2[(size_t)NR * DW];   // 21 MB ELL (dendrite L2)
__device__ int4 g_cntQ1[NR];   // entry counts at col <256,<512,<768,total
__device__ int4 g_cntQ2[NR];
__device__ __align__(16) u64 g_ellF1[(size_t)HID * FW];  // 3 MB  ELL (ff L1)
__device__ __align__(16) u64 g_ellF2[(size_t)HID * FW];  // 3 MB  ELL (ff L2)
__device__ int  g_cntF1[HID];
__device__ int  g_cntF2[HID];

// =====================================================================
// warp-per-row ELL compaction: ballot+popc positioning, depth-2
// register prefetch (4 LDG.128 in flight). Ascending column order.
// entry = (f32 weight bits << 32) | (col * mult).
// cq != 0: also record counts at chunk boundaries 2,4,6 (cols 256/512/768).
// =====================================================================
__device__ __forceinline__
void build_row(const float* __restrict__ W, const float* __restrict__ M,
               u64* __restrict__ ell, int* __restrict__ cnt, int4* __restrict__ cq,
               int K, int width, int mult, int row, int lane) {
    const float4* wr = (const float4*)(W + (size_t)row * K);
    const float4* mr = (const float4*)(M + (size_t)row * K);
    u64* er = ell + (size_t)row * width;
    const int chunks = K >> 7;  // 128 floats per chunk (float4 per lane)
    const unsigned below = (1u << lane) - 1u;
    int base = 0, q1 = 0, q2 = 0, q3 = 0;
    float4 w0 = wr[lane],      m0 = mr[lane];
    float4 w1 = wr[32 + lane], m1 = mr[32 + lane];  // chunks >= 4 always
    for (int c = 0; c < chunks; ++c) {
        float4 wn, mn;
        if (c + 2 < chunks) {
            wn = wr[(c + 2) * 32 + lane];
            mn = mr[(c + 2) * 32 + lane];
        }
        const unsigned bx = __ballot_sync(0xffffffffu, m0.x != 0.f);
        const unsigned by = __ballot_sync(0xffffffffu, m0.y != 0.f);
        const unsigned bz = __ballot_sync(0xffffffffu, m0.z != 0.f);
        const unsigned bw = __ballot_sync(0xffffffffu, m0.w != 0.f);
        int p = base + __popc(bx & below) + __popc(by & below)
                     + __popc(bz & below) + __popc(bw & below);
        const int col0 = c * 128 + lane * 4;
        if (m0.x != 0.f && p < width) er[p++] = ((u64)__float_as_uint(w0.x) << 32) | (unsigned)((col0 + 0) * mult);
        if (m0.y != 0.f && p < width) er[p++] = ((u64)__float_as_uint(w0.y) << 32) | (unsigned)((col0 + 1) * mult);
        if (m0.z != 0.f && p < width) er[p++] = ((u64)__float_as_uint(w0.z) << 32) | (unsigned)((col0 + 2) * mult);
        if (m0.w != 0.f && p < width) er[p++] = ((u64)__float_as_uint(w0.w) << 32) | (unsigned)((col0 + 3) * mult);
        base += __popc(bx) + __popc(by) + __popc(bz) + __popc(bw);
        if (c == 1) q1 = base;
        else if (c == 3) q2 = base;
        else if (c == 5) q3 = base;
        w0 = w1; m0 = m1;
        w1 = wn; m1 = mn;
    }
    if (lane == 0) {
        const int t = base < width ? base : width;
        if (cq) cq[row] = make_int4(q1 < width ? q1 : width,
                                    q2 < width ? q2 : width,
                                    q3 < width ? q3 : width, t);
        else cnt[row] = t;
    }
}

// =====================================================================
// K1a: fused builds only.
// Dendrite entries: mult=512 (128-batch float4 tile), quarter bounds.
// FF entries: mult=1024 (256-batch float tile).
// Block ranges:
//   [0,2560)      build dendrite L1   (8 rows/block)
//   [2560,5120)   build dendrite L2
//   [5120,5376)   build FF L1
//   [5376,5632)   build FF L2
// =====================================================================
__global__ __launch_bounds__(256)
void prep_build(const float* __restrict__ segW1, const float* __restrict__ maskS1,
                const float* __restrict__ segW2, const float* __restrict__ maskS2,
                const float* __restrict__ W1, const float* __restrict__ maskW1,
                const float* __restrict__ W2, const float* __restrict__ maskW2) {
    const int bid = blockIdx.x;
    const int tid = threadIdx.x;
    const int lane = tid & 31;
    const int wid = tid >> 5;

    if (bid < 5120) {  // dendrite builds
        const int part = bid / 2560;                 // 0 or 1
        const int row = (bid % 2560) * 8 + wid;      // 0..20479
        if (part == 0) build_row(segW1, maskS1, g_ellD1, (int*)0, g_cntQ1, DCTX, DW, 512, row, lane);
        else           build_row(segW2, maskS2, g_ellD2, (int*)0, g_cntQ2, DCTX, DW, 512, row, lane);
        return;
    }
    // FF builds
    const int part = (bid - 5120) >> 8;              // 0 or 1 (256 blocks each)
    const int row = ((bid - 5120) & 255) * 8 + wid;
    if (part == 0) build_row(W1, maskW1, g_ellF1, g_cntF1, (int4*)0, DIN, FW, 1024, row, lane);
    else           build_row(W2, maskW2, g_ellF2, g_cntF2, (int4*)0, HID, FW, 1024, row, lane);
}

// =====================================================================
// K1b: both transposes. Block ranges: [0,256) ctx, [256,768) x.
// in[R=256][C] -> out[C][256]
// =====================================================================
__global__ __launch_bounds__(256)
void prep_transpose(const float* __restrict__ ctx, const float* __restrict__ x) {
    __shared__ float t[32][33];
    const int bid = blockIdx.x;
    const int tid = threadIdx.x;
    const float* in;
    float* outp;
    int C, lb;
    if (bid < 256) { in = ctx; outp = g_ctxT; C = DCTX; lb = bid; }
    else           { in = x;   outp = g_xT;   C = DIN;  lb = bid - 256; }
    const int nbx = C >> 5;
    const int c0 = (lb % nbx) * 32;
    const int r0 = (lb / nbx) * 32;
    const int xx = tid & 31, yy = tid >> 5;
#pragma unroll
    for (int i = 0; i < 32; i += 8)
        t[yy + i][xx] = in[(size_t)(r0 + yy + i) * C + c0 + xx];
    __syncthreads();
#pragma unroll
    for (int i = 0; i < 32; i += 8)
        outp[(size_t)(c0 + yy + i) * BDIM + r0 + xx] = t[xx][yy + i];
}

// =====================================================================
// K2: fused dendrite spMM + gate, 128-batch / 4-c-pass, 32 warps/SM.
// 1024 threads (32 warps, 64-reg budget); warp = ONE unit; lane = 4
// batches (float4 LDS.128). accs = 10 x float4 = 40 regs; unroll-2
// inner loop keeps live set < 64 regs (no spill).
// smem tile = ctx[256 c][128 b] = 128 KB, swapped across 4 passes;
// entries split at quarter boundaries.
// grid 256: [layer(2)][bg(2)][blk(64) x 32 warps = 2048 units].
//   <-- PROFILED (user slot 4)
// =====================================================================
__global__ __launch_bounds__(1024, 1)
void dspmm_gate2(const float* __restrict__ ctxT) {
    extern __shared__ float s[];  // 256 * 128 floats = 128 KB
    const int id = blockIdx.x;
    const int layer = id >> 7;
    const int bg = (id >> 6) & 1;
    const int blk = id & 63;
    const u64* __restrict__ ell = layer ? g_ellD2 : g_ellD1;
    const int4* __restrict__ cq = layer ? g_cntQ2 : g_cntQ1;
    float* __restrict__ gT = layer ? g_gT2 : g_gT1;

    const int b0 = bg * 128;
    const int tid = threadIdx.x;
    const int wid = tid >> 5, lane = tid & 31;
    const char* sb = (const char*)s + lane * 16;
    const int u = blk * 32 + wid;            // one unit per warp
    const int r0 = u * NSEG;
    int4 q = make_int4(0, 0, 0, 0);
    if (lane < NSEG) q = cq[r0 + lane];

    float4 accs[NSEG];
#pragma unroll
    for (int sg = 0; sg < NSEG; ++sg) accs[sg] = make_float4(0.f, 0.f, 0.f, 0.f);

#pragma unroll
    for (int pass = 0; pass < 4; ++pass) {
        if (pass) __syncthreads();  // all warps done reading previous tile
        // stage ctx[pass*256 .. +256)[b0 .. b0+127]
        for (int i = tid; i < 256 * 32; i += 1024) {
            const int c = i >> 5, qq = (i & 31) * 4;
            *(float4*)&s[c * 128 + qq] =
                *(const float4*)&ctxT[(size_t)(pass * 256 + c) * 256 + b0 + qq];
        }
        __syncthreads();
        // per-lane boundary pair for this pass (own row)
        const int jlo_own = (pass == 0) ? 0 : ((pass == 1) ? q.x : ((pass == 2) ? q.y : q.z));
        const int jhi_own = (pass == 0) ? q.x : ((pass == 1) ? q.y : ((pass == 2) ? q.z : q.w));
        const unsigned off = (unsigned)pass * 131072u;  // 256 cols * 512 B
#pragma unroll
        for (int sg = 0; sg < NSEG; ++sg) {
            const int j0 = __shfl_sync(0xffffffffu, jlo_own, sg);
            const int j1 = __shfl_sync(0xffffffffu, jhi_own, sg);
            const u64* e = ell + (size_t)(r0 + sg) * DW;
            float4 a = accs[sg];
            int j = j0;
            for (; j + 2 <= j1; j += 2) {
                const u64 e0 = e[j], e1 = e[j + 1];
                const float w0 = __uint_as_float((unsigned)(e0 >> 32));
                const float w1 = __uint_as_float((unsigned)(e1 >> 32));
                const float4 v0 = *(const float4*)(sb + ((unsigned)e0 - off));
                const float4 v1 = *(const float4*)(sb + ((unsigned)e1 - off));
                a.x += w0 * v0.x; a.y += w0 * v0.y; a.z += w0 * v0.z; a.w += w0 * v0.w;
                a.x += w1 * v1.x; a.y += w1 * v1.y; a.z += w1 * v1.z; a.w += w1 * v1.w;
            }
            if (j < j1) {
                const u64 e0 = e[j];
                const float w0 = __uint_as_float((unsigned)(e0 >> 32));
                const float4 v0 = *(const float4*)(sb + ((unsigned)e0 - off));
                a.x += w0 * v0.x; a.y += w0 * v0.y; a.z += w0 * v0.z; a.w += w0 * v0.w;
            }
            accs[sg] = a;
        }
    }
    // first-occurrence abs-argmax (strict >) + sigmoid, per batch component
    float4 best = accs[0];
    float4 ba = make_float4(fabsf(best.x), fabsf(best.y), fabsf(best.z), fabsf(best.w));
#pragma unroll
    for (int sg = 1; sg < NSEG; ++sg) {
        const float4 v = accs[sg];
        float a;
        a = fabsf(v.x); if (a > ba.x) { ba.x = a; best.x = v.x; }
        a = fabsf(v.y); if (a > ba.y) { ba.y = a; best.y = v.y; }
        a = fabsf(v.z); if (a > ba.z) { ba.z = a; best.z = v.z; }
        a = fabsf(v.w); if (a > ba.w) { ba.w = a; best.w = v.w; }
    }
    const float4 g = make_float4(1.0f / (1.0f + __expf(-best.x)),
                                 1.0f / (1.0f + __expf(-best.y)),
                                 1.0f / (1.0f + __expf(-best.z)),
                                 1.0f / (1.0f + __expf(-best.w)));
    *(float4*)&gT[(size_t)u * 256 + b0 + lane * 4] = g;
}

// =====================================================================
// FF spMM (gate applied in kwinners): yT[r][b] = bias[r] + sum w*xT[c][b]
// One block per output row (2048 blocks); entries staged in smem (16B
// aligned), read back as LDS.128 pairs; unroll 8 for L2 MLP.
// =====================================================================
__global__ __launch_bounds__(256)
void fspmm(const float* __restrict__ xT, const u64* __restrict__ ell,
           const int* __restrict__ cnt, const float* __restrict__ bias,
           float* __restrict__ yT) {
    __shared__ alignas(16) u64 fe[FW];
    const int r = blockIdx.x;
    const int tid = threadIdx.x;
    const int n = cnt[r];
    for (int j = tid; j < n; j += 256) fe[j] = ell[(size_t)r * FW + j];
    __syncthreads();
    const char* xb = (const char*)xT + tid * 4;
    const ulonglong2* fe2 = (const ulonglong2*)fe;
    float acc = 0.f;
    int j = 0;
    for (; j + 8 <= n; j += 8) {
        float p = 0.f;
#pragma unroll
        for (int q = 0; q < 4; ++q) {
            const ulonglong2 e = fe2[(j >> 1) + q];
            p += __uint_as_float((unsigned)(e.x >> 32)) * *(const float*)(xb + (unsigned)e.x);
            p += __uint_as_float((unsigned)(e.y >> 32)) * *(const float*)(xb + (unsigned)e.y);
        }
        acc += p;
    }
    for (; j < n; ++j) {
        const u64 e = fe[j];
        acc += __uint_as_float((unsigned)(e >> 32)) * *(const float*)(xb + (unsigned)e);
    }
    yT[(size_t)r * 256 + tid] = acc + bias[r];
}

// =====================================================================
// k-winners with fused gate: val = yT[i][b] * gT[i][b]; exact top-KWIN
// via 4-pass radix select; single-warp shfl suffix scan bin selection.
// mode 0 -> transposed hT[i][b]; mode 1 -> row-major h2[b][i].
// =====================================================================
__global__ __launch_bounds__(256)
void kwinners_k(const float* __restrict__ yT, const float* __restrict__ gT,
                float* __restrict__ outT, float* __restrict__ outN, int mode) {
    __shared__ unsigned keys[HID];
    __shared__ int hist[256];
    __shared__ int s_digit;
    __shared__ int s_need;
    const int b = blockIdx.x, tid = threadIdx.x;
    for (int i = tid; i < HID; i += 256) {
        const float v = yT[(size_t)i * 256 + b] * gT[(size_t)i * 256 + b];
        unsigned u = __float_as_uint(v);
        u = (u & 0x80000000u) ? ~u : (u | 0x80000000u);  // monotonic ascending
        keys[i] = u;
    }
    if (tid == 0) s_need = KWIN;
    __syncthreads();

    unsigned prefix = 0, pmask = 0;
    for (int pass = 0; pass < 4; ++pass) {
        const int shift = 24 - 8 * pass;
        hist[tid] = 0;
        __syncthreads();
        for (int i = tid; i < HID; i += 256) {
            const unsigned u = keys[i];
            if ((u & pmask) == prefix) atomicAdd(&hist[(u >> shift) & 255], 1);
        }
        __syncthreads();
        if (tid < 32) {
            const int need = s_need;
            const int base = tid * 8;
            int gs = 0;
#pragma unroll
            for (int k = 0; k < 8; ++k) gs += hist[base + k];
            int S = gs;  // inclusive suffix sum across lanes
#pragma unroll
            for (int o = 1; o < 32; o <<= 1) {
                const int t = __shfl_down_sync(0xffffffffu, S, o);
                if (tid + o < 32) S += t;
            }
            int Snext = __shfl_down_sync(0xffffffffu, S, 1);
            if (tid == 31) Snext = 0;
            if (S >= need && Snext < need) {  // unique crossing lane
                int c = Snext;
#pragma unroll
                for (int k = 7; k >= 0; --k) {
                    const int hb = hist[base + k];
                    if (c + hb >= need) { s_digit = base + k; s_need = need - c; break; }
                    c += hb;
                }
            }
        }
        __syncthreads();
        prefix |= ((unsigned)s_digit) << shift;
        pmask |= 0xFFu << shift;
    }
    const unsigned thr = prefix;  // key of the KWIN-th largest
    for (int i = tid; i < HID; i += 256) {
        const unsigned u = keys[i];
        float val = 0.f;
        if (u >= thr) {
            const unsigned ob = (u & 0x80000000u) ? (u & 0x7FFFFFFFu) : ~u;
            val = __uint_as_float(ob);
        }
        if (mode == 0) outT[(size_t)i * 256 + b] = val;
        else           outN[(size_t)b * HID + i] = val;
    }
}

// =====================================================================
// EiDense head: out[b,o] = h.Wex[o] - (h.Wix)*Wei[o] + b_out[o]
// =====================================================================
__global__ __launch_bounds__(256)
void head_kernel(const float* __restrict__ h, const float* __restrict__ Wex,
                 const float* __restrict__ Wix, const float* __restrict__ Wei,
                 const float* __restrict__ bo, float* __restrict__ out) {
    __shared__ alignas(16) float sh[4][HID];
    __shared__ float st[4];
    const int b0 = blockIdx.x * 4;
    const int tid = threadIdx.x;
    for (int i = tid; i < 4 * HID; i += 256)
        (&sh[0][0])[i] = h[(size_t)b0 * HID + i];
    __syncthreads();
    const int wid = tid >> 5;
    const int lane = tid & 31;
    if (wid < 4) {
        float p = 0.f;
        for (int u = lane; u < HID; u += 32) p += sh[wid][u] * Wix[u];
#pragma unroll
        for (int o = 16; o; o >>= 1) p += __shfl_xor_sync(0xffffffffu, p, o);
        if (lane == 0) st[wid] = p;
    }
    __syncthreads();
    for (int o = wid; o < OUTD; o += 8) {
        float a0 = 0.f, a1 = 0.f, a2 = 0.f, a3 = 0.f;
        const float* wrow = Wex + (size_t)o * HID;
        for (int u = lane; u < HID; u += 32) {
            const float w = wrow[u];
            a0 += sh[0][u] * w;
            a1 += sh[1][u] * w;
            a2 += sh[2][u] * w;
            a3 += sh[3][u] * w;
        }
#pragma unroll
        for (int sft = 16; sft; sft >>= 1) {
            a0 += __shfl_xor_sync(0xffffffffu, a0, sft);
            a1 += __shfl_xor_sync(0xffffffffu, a1, sft);
            a2 += __shfl_xor_sync(0xffffffffu, a2, sft);
            a3 += __shfl_xor_sync(0xffffffffu, a3, sft);
        }
        if (lane == 0) {
            const float we = Wei[o];
            const float bb = bo[o];
            out[(size_t)(b0 + 0) * OUTD + o] = a0 - st[0] * we + bb;
            out[(size_t)(b0 + 1) * OUTD + o] = a1 - st[1] * we + bb;
            out[(size_t)(b0 + 2) * OUTD + o] = a2 - st[2] * we + bb;
            out[(size_t)(b0 + 3) * OUTD + o] = a3 - st[3] * we + bb;
        }
    }
}

// =====================================================================
// launch — dspmm_gate2 kept at user-launch #4 (ncu -s 5 slot)
// =====================================================================
extern "C" void kernel_launch(void* const* d_in, const int* in_sizes, int n_in,
                              void* d_out, int out_size) {
    const float* x      = (const float*)d_in[0];
    const float* ctx    = (const float*)d_in[1];
    const float* W1     = (const float*)d_in[2];
    const float* b1     = (const float*)d_in[3];
    const float* segW1  = (const float*)d_in[4];
    const float* maskW1 = (const float*)d_in[5];
    const float* maskS1 = (const float*)d_in[6];
    const float* W2     = (const float*)d_in[7];
    const float* b2     = (const float*)d_in[8];
    const float* segW2  = (const float*)d_in[9];
    const float* maskW2 = (const float*)d_in[10];
    const float* maskS2 = (const float*)d_in[11];
    const float* Wex    = (const float*)d_in[12];
    const float* Wix    = (const float*)d_in[13];
    const float* Wei    = (const float*)d_in[14];
    const float* bo     = (const float*)d_in[15];
    float* out = (float*)d_out;

    float *ctxT, *xT, *hT, *yT, *gT1, *gT2, *h2;
    u64 *ellF1, *ellF2;
    int *cntF1, *cntF2;
    cudaGetSymbolAddress((void**)&ctxT,  g_ctxT);
    cudaGetSymbolAddress((void**)&xT,    g_xT);
    cudaGetSymbolAddress((void**)&hT,    g_hT);
    cudaGetSymbolAddress((void**)&yT,    g_yT);
    cudaGetSymbolAddress((void**)&gT1,   g_gT1);
    cudaGetSymbolAddress((void**)&gT2,   g_gT2);
    cudaGetSymbolAddress((void**)&h2,    g_h2);
    cudaGetSymbolAddress((void**)&ellF1, g_ellF1);
    cudaGetSymbolAddress((void**)&ellF2, g_ellF2);
    cudaGetSymbolAddress((void**)&cntF1, g_cntF1);
    cudaGetSymbolAddress((void**)&cntF2, g_cntF2);

    const int dsmem = 256 * 128 * 4;  // 128 KB
    cudaFuncSetAttribute(dspmm_gate2, cudaFuncAttributeMaxDynamicSharedMemorySize, dsmem);

    // (1) all four ELL builds fused (ballot-scan, depth-2 prefetch,
    //     +quarter boundaries for dendrites)
    prep_build<<<5632, 256>>>(segW1, maskS1, segW2, maskS2,
                              W1, maskW1, W2, maskW2);
    // (2) both transposes
    prep_transpose<<<768, 256>>>(ctx, x);
    // (3) layer 1 FF (independent of dendrite path)
    fspmm<<<HID, 256>>>(xT, ellF1, cntF1, b1, yT);
    // (4) both layers' dendrite gates, 128-batch / 4-pass / 32 warps/SM
    dspmm_gate2<<<256, 1024, dsmem>>>(ctxT);   // <-- ncu slot
    // (5) layer 1 k-winners (applies gate 1) -> hT
    kwinners_k<<<BDIM, 256>>>(yT, gT1, hT, h2, 0);
    // (6) layer 2 FF
    fspmm<<<HID, 256>>>(hT, ellF2, cntF2, b2, yT);
    // (7) layer 2 k-winners (applies gate 2) -> h2 row-major
    kwinners_k<<<BDIM, 256>>>(yT, gT2, hT, h2, 1);
    // (8) EiDense head
    head_kernel<<<BDIM / 4, 256>>>(h2, Wex, Wix, Wei, bo, out);
}